// round 3
// baseline (speedup 1.0000x reference)
#include <cuda_runtime.h>
#include <cuda_bf16.h>

// Shapes (fixed)
#define B_   32
#define P_   16
#define S_   256
#define D_   256
#define NG_  128
#define N_   4096
#define E_   65536
#define H_   256

#define NBLK 128
#define NTHR 256

// ---------------- scratch ----------------------------------------------------
__device__ __align__(16) float g_node_x[N_ * D_];
__device__ float g_dis[N_];
__device__ int   g_cnt[N_];
__device__ int   g_cursor[N_];
__device__ int   g_offs[N_ + 1];
__device__ int   g_csr_src[E_];
__device__ float g_csr_w[E_];
__device__ __align__(16) float g_agg[N_ * D_];
__device__ __align__(16) float g_x1[N_ * H_];
__device__ float g_C[N_ * B_];
__device__ __align__(16) float g_part[NBLK * B_ * H_];
__device__ float g_tmp[B_ * H_];

// grid barrier state (zero-init at module load; self-restoring across launches)
__device__ unsigned g_barcnt;
__device__ unsigned g_barrel;

__device__ __forceinline__ void gbar(unsigned gen0, unsigned k) {
    __syncthreads();
    if (threadIdx.x == 0) {
        __threadfence();
        unsigned a = atomicAdd(&g_barcnt, 1u);
        if (a == NBLK - 1u) {
            g_barcnt = 0;
            __threadfence();
            atomicAdd(&g_barrel, 1u);
        } else {
            // bounded spin: never hang the container; 50M iters >> any real wait
            for (long long it = 0; it < 50000000LL; ++it) {
                unsigned cur = *(volatile unsigned*)&g_barrel;
                if (cur - gen0 >= k) break;
                __nanosleep(32);
            }
        }
        __threadfence();
    }
    __syncthreads();
}

// packed fp32x2 helpers (sm_103a dual-issue fp32 pipe)
__device__ __forceinline__ unsigned long long ffma2(unsigned long long a,
                                                    unsigned long long b,
                                                    unsigned long long c) {
    unsigned long long d;
    asm("fma.rn.f32x2 %0, %1, %2, %3;" : "=l"(d) : "l"(a), "l"(b), "l"(c));
    return d;
}
__device__ __forceinline__ unsigned long long pk2(float x) {
    unsigned long long r; unsigned u = __float_as_uint(x);
    asm("mov.b64 %0, {%1, %2};" : "=l"(r) : "r"(u), "r"(u));
    return r;
}

__global__ void __launch_bounds__(NTHR)
fused_kernel(const float* __restrict__ dge, const int* __restrict__ gids,
             const int* __restrict__ ei,
             const float* __restrict__ W1, const float* __restrict__ b1,
             const float* __restrict__ W2, const float* __restrict__ b2,
             float* __restrict__ out) {
    const int tid = threadIdx.x;
    const int bid = blockIdx.x;
    const int idx = bid * NTHR + tid;    // 0..32767

    unsigned gen0 = 0;
    if (tid == 0) gen0 = *(volatile unsigned*)&g_barrel;

    __shared__ __align__(16) int   s_src[256];
    __shared__ __align__(16) float s_w[256];
    __shared__ __align__(16) int   s_scan[256];
    __shared__ __align__(16) float sC[32][33];
    __shared__ __align__(16) float As[16][132];   // row stride 132*4=528B (16B mult)
    __shared__ __align__(16) float Bs[16][68];    // row stride 272B (16B mult)

    // ---- P0: zero cnt / cursor / C --------------------------------------
    if (idx < N_) { g_cnt[idx] = 0; g_cursor[idx] = 0; }
    for (int i = idx; i < N_ * B_; i += NBLK * NTHR) g_C[i] = 0.0f;

    gbar(gen0, 1);

    // ---- P1: degree histogram -------------------------------------------
    for (int e = idx; e < E_; e += NBLK * NTHR)
        atomicAdd(&g_cnt[ei[E_ + e]], 1);

    gbar(gen0, 2);

    // ---- P2: dis (blocks 1..16) + exclusive scan (block 0) --------------
    if (bid == 0) {
        int base = tid * 16;
        int vals[16]; int tot = 0;
#pragma unroll
        for (int j = 0; j < 16; j++) { vals[j] = g_cnt[base + j]; tot += vals[j]; }
        s_scan[tid] = tot;
        __syncthreads();
        for (int off = 1; off < 256; off <<= 1) {
            int x = (tid >= off) ? s_scan[tid - off] : 0;
            __syncthreads();
            s_scan[tid] += x;
            __syncthreads();
        }
        int excl = s_scan[tid] - tot;
#pragma unroll
        for (int j = 0; j < 16; j++) { g_offs[base + j] = excl; excl += vals[j]; }
        if (tid == 255) g_offs[N_] = excl;
    } else if (bid <= 16) {
        int i = (bid - 1) * NTHR + tid;
        float dv = rsqrtf((float)(g_cnt[i] + 1));   // +1 self-loop
        g_dis[i] = dv;
        g_C[i * B_ + (i >> 7)] = dv * dv;           // self-loop seed into C
    }

    gbar(gen0, 3);

    // ---- P3: scatter edges into CSR + C; node_mean (independent work) ---
    for (int e = idx; e < E_; e += NBLK * NTHR) {
        int u = ei[e];
        int v = ei[E_ + e];
        float w = g_dis[u] * g_dis[v];
        int pos = g_offs[v] + atomicAdd(&g_cursor[v], 1);
        g_csr_src[pos] = u;
        g_csr_w[pos]   = w;
        atomicAdd(&g_C[u * B_ + (v >> 7)], w);
    }
    {   // node_mean: 32 nodes per block, float4 lanes, 16-deep MLP
        const int lane = tid & 63, sub = tid >> 6;
        const float inv = 1.0f / (float)P_;
#pragma unroll
        for (int r = 0; r < 8; r++) {
            int n = bid * 32 + r * 4 + sub;
            int b = n >> 7;
            int g = gids[n];
            const float4* base = (const float4*)(dge + ((size_t)(b * P_ * S_ + g)) * D_) + lane;
            float sx = 0, sy = 0, sz = 0, sw = 0;
#pragma unroll
            for (int p = 0; p < P_; p++) {
                float4 v = base[p * (S_ * D_ / 4)];
                sx += v.x; sy += v.y; sz += v.z; sw += v.w;
            }
            float4 o; o.x = sx * inv; o.y = sy * inv; o.z = sz * inv; o.w = sw * inv;
            ((float4*)g_node_x)[n * (D_ / 4) + lane] = o;
        }
    }

    gbar(gen0, 4);

    // ---- P4: aggregate (gather over CSR), 32 v per block ----------------
    for (int vv = 0; vv < 32; vv++) {
        int v = bid * 32 + vv;
        int beg = g_offs[v], end = g_offs[v + 1];
        float dv = g_dis[v];
        float acc = dv * dv * g_node_x[v * D_ + tid];
        for (int base = beg; base < end; base += 256) {
            int nn = end - base; if (nn > 256) nn = 256;
            __syncthreads();
            if (tid < nn) { s_src[tid] = g_csr_src[base + tid]; s_w[tid] = g_csr_w[base + tid]; }
            __syncthreads();
            float a0 = 0, a1 = 0, a2 = 0, a3 = 0, a4 = 0, a5 = 0, a6 = 0, a7 = 0;
            int i = 0;
            for (; i + 8 <= nn; i += 8) {
                a0 += s_w[i + 0] * g_node_x[s_src[i + 0] * D_ + tid];
                a1 += s_w[i + 1] * g_node_x[s_src[i + 1] * D_ + tid];
                a2 += s_w[i + 2] * g_node_x[s_src[i + 2] * D_ + tid];
                a3 += s_w[i + 3] * g_node_x[s_src[i + 3] * D_ + tid];
                a4 += s_w[i + 4] * g_node_x[s_src[i + 4] * D_ + tid];
                a5 += s_w[i + 5] * g_node_x[s_src[i + 5] * D_ + tid];
                a6 += s_w[i + 6] * g_node_x[s_src[i + 6] * D_ + tid];
                a7 += s_w[i + 7] * g_node_x[s_src[i + 7] * D_ + tid];
            }
            for (; i < nn; i++) a0 += s_w[i] * g_node_x[s_src[i] * D_ + tid];
            acc += ((a0 + a1) + (a2 + a3)) + ((a4 + a5) + (a6 + a7));
        }
        __syncthreads();
        g_agg[v * D_ + tid] = acc;
    }

    gbar(gen0, 5);

    // ---- P5: x1 = relu(agg @ W1 + b1); 128x64 tile per block, FFMA2 -----
    {
        int m0 = (bid >> 2) * 128, n0 = (bid & 3) * 64;
        int tx = tid & 15, ty = tid >> 4;
        unsigned long long acc[4][4];
#pragma unroll
        for (int p = 0; p < 4; p++)
#pragma unroll
            for (int j = 0; j < 4; j++) acc[p][j] = 0ull;

        for (int k0 = 0; k0 < 256; k0 += 16) {
#pragma unroll
            for (int q = 0; q < 2; q++) {
                int li = tid + q * 256;
                int m = li >> 2, kq = (li & 3) << 2;
                float4 a = *(const float4*)&g_agg[(m0 + m) * 256 + k0 + kq];
                As[kq + 0][m] = a.x; As[kq + 1][m] = a.y;
                As[kq + 2][m] = a.z; As[kq + 3][m] = a.w;
            }
            {
                int row = tid >> 4, nq = (tid & 15) << 2;
                *(float4*)&Bs[row][nq] = *(const float4*)&W1[(k0 + row) * 256 + n0 + nq];
            }
            __syncthreads();
#pragma unroll
            for (int kk = 0; kk < 16; kk++) {
                ulonglong2 A0 = *(const ulonglong2*)&As[kk][ty * 8];
                ulonglong2 A1 = *(const ulonglong2*)&As[kk][ty * 8 + 4];
                float4 bv = *(const float4*)&Bs[kk][tx * 4];
                unsigned long long p0 = pk2(bv.x), p1 = pk2(bv.y), p2 = pk2(bv.z), p3 = pk2(bv.w);
                acc[0][0] = ffma2(A0.x, p0, acc[0][0]); acc[0][1] = ffma2(A0.x, p1, acc[0][1]);
                acc[0][2] = ffma2(A0.x, p2, acc[0][2]); acc[0][3] = ffma2(A0.x, p3, acc[0][3]);
                acc[1][0] = ffma2(A0.y, p0, acc[1][0]); acc[1][1] = ffma2(A0.y, p1, acc[1][1]);
                acc[1][2] = ffma2(A0.y, p2, acc[1][2]); acc[1][3] = ffma2(A0.y, p3, acc[1][3]);
                acc[2][0] = ffma2(A1.x, p0, acc[2][0]); acc[2][1] = ffma2(A1.x, p1, acc[2][1]);
                acc[2][2] = ffma2(A1.x, p2, acc[2][2]); acc[2][3] = ffma2(A1.x, p3, acc[2][3]);
                acc[3][0] = ffma2(A1.y, p0, acc[3][0]); acc[3][1] = ffma2(A1.y, p1, acc[3][1]);
                acc[3][2] = ffma2(A1.y, p2, acc[3][2]); acc[3][3] = ffma2(A1.y, p3, acc[3][3]);
            }
            __syncthreads();
        }
        float bb[4];
#pragma unroll
        for (int j = 0; j < 4; j++) bb[j] = b1[n0 + tx * 4 + j];
#pragma unroll
        for (int p = 0; p < 4; p++) {
            int m = m0 + ty * 8 + p * 2;
#pragma unroll
            for (int j = 0; j < 4; j++) {
                float lo = __uint_as_float((unsigned)(acc[p][j] & 0xffffffffull));
                float hi = __uint_as_float((unsigned)(acc[p][j] >> 32));
                int nc = n0 + tx * 4 + j;
                g_x1[m * 256 + nc]       = fmaxf(lo + bb[j], 0.0f);
                g_x1[(m + 1) * 256 + nc] = fmaxf(hi + bb[j], 0.0f);
            }
        }
    }

    gbar(gen0, 6);

    // ---- P6: pool partials: part[bid][b][d] = sum_{u in slice} C[u][b]*x1[u][d]
    {
        int u0 = bid * 32;
        for (int i = tid; i < 32 * 32; i += NTHR) sC[i >> 5][i & 31] = g_C[u0 * 32 + i];
        __syncthreads();
        float pacc[32];
#pragma unroll
        for (int b = 0; b < 32; b++) pacc[b] = 0.0f;
        int d = tid;
        for (int uu = 0; uu < 32; uu++) {
            float x = g_x1[(u0 + uu) * 256 + d];
#pragma unroll
            for (int b = 0; b < 32; b++) pacc[b] += sC[uu][b] * x;
        }
#pragma unroll
        for (int b = 0; b < 32; b++) g_part[bid * (B_ * H_) + b * 256 + d] = pacc[b];
    }

    gbar(gen0, 7);

    // ---- P7: reduce partials -> tmp -------------------------------------
    if (idx < B_ * H_) {
        float s = 0.0f;
#pragma unroll 8
        for (int k = 0; k < NBLK; k++) s += g_part[k * (B_ * H_) + idx];
        g_tmp[idx] = s;
    }

    gbar(gen0, 8);

    // ---- P8: out = tmp @ W2 / NG + b2 -----------------------------------
    if (idx < B_ * H_) {
        int b = idx >> 8, h = idx & 255;
        const float* tr = g_tmp + b * 256;
        float acc = 0.0f;
#pragma unroll 8
        for (int d = 0; d < 256; d++) acc += tr[d] * W2[d * 256 + h];
        out[idx] = acc * (1.0f / NG_) + b2[h];
    }
}

// ---------------- launch -----------------------------------------------------
extern "C" void kernel_launch(void* const* d_in, const int* in_sizes, int n_in,
                              void* d_out, int out_size) {
    const float* dge  = (const float*)d_in[0];
    const int*   gids = (const int*)  d_in[1];
    const int*   ei   = (const int*)  d_in[2];
    const float* W1   = (const float*)d_in[3];
    const float* b1   = (const float*)d_in[4];
    const float* W2   = (const float*)d_in[5];
    const float* b2   = (const float*)d_in[6];
    float* out = (float*)d_out;

    fused_kernel<<<NBLK, NTHR>>>(dge, gids, ei, W1, b1, W2, b2, out);
}

// round 4
// speedup vs baseline: 1.2838x; 1.2838x over previous
#include <cuda_runtime.h>
#include <cuda_bf16.h>

// Shapes (fixed)
#define B_   32
#define P_   16
#define S_   256
#define D_   256
#define NG_  128
#define N_   4096
#define E_   65536
#define H_   256

#define NBLK 128
#define NTHR 512

// ---------------- scratch ----------------------------------------------------
__device__ __align__(16) float g_node_x[N_ * D_];
__device__ float g_dis[N_];
__device__ int   g_cnt[N_];
__device__ int   g_cursor[N_];
__device__ int   g_offs[N_ + 1];
__device__ __align__(16) int   g_csr_src[E_];
__device__ __align__(16) float g_csr_w[E_];
__device__ __align__(16) float g_agg[N_ * D_];
__device__ __align__(16) float g_x1[N_ * H_];
__device__ float g_C[N_ * B_];
__device__ __align__(16) float g_part[NBLK * 2 * B_ * H_];   // 256 slots x 8192
__device__ float g_tmp[B_ * H_];

// grid barrier state (zero-init at module load; self-restoring across launches)
__device__ unsigned g_barcnt;
__device__ unsigned g_barrel;

__device__ __forceinline__ void gbar(unsigned gen0, unsigned k) {
    __syncthreads();
    if (threadIdx.x == 0) {
        __threadfence();
        unsigned a = atomicAdd(&g_barcnt, 1u);
        if (a == NBLK - 1u) {
            g_barcnt = 0;
            __threadfence();
            atomicAdd(&g_barrel, 1u);
        } else {
            for (long long it = 0; it < 50000000LL; ++it) {   // bounded: never hang
                unsigned cur = *(volatile unsigned*)&g_barrel;
                if (cur - gen0 >= k) break;
                __nanosleep(32);
            }
        }
        __threadfence();
    }
    __syncthreads();
}

// packed fp32x2 helpers
__device__ __forceinline__ unsigned long long ffma2(unsigned long long a,
                                                    unsigned long long b,
                                                    unsigned long long c) {
    unsigned long long d;
    asm("fma.rn.f32x2 %0, %1, %2, %3;" : "=l"(d) : "l"(a), "l"(b), "l"(c));
    return d;
}
__device__ __forceinline__ unsigned long long pk2(float x) {
    unsigned long long r; unsigned u = __float_as_uint(x);
    asm("mov.b64 %0, {%1, %2};" : "=l"(r) : "r"(u), "r"(u));
    return r;
}

__global__ void __launch_bounds__(NTHR)
fused_kernel(const float* __restrict__ dge, const int* __restrict__ gids,
             const int* __restrict__ ei,
             const float* __restrict__ W1, const float* __restrict__ b1,
             const float* __restrict__ W2, const float* __restrict__ b2,
             float* __restrict__ out) {
    const int tid = threadIdx.x;
    const int bid = blockIdx.x;
    const int idx = bid * NTHR + tid;    // 0..65535

    unsigned gen0 = 0;
    if (tid == 0) gen0 = *(volatile unsigned*)&g_barrel;

    __shared__ __align__(16) int   s_scan[NTHR];
    __shared__ __align__(16) float sC[32][33];
    __shared__ __align__(16) float As[16][132];   // [k][m], stride 528B
    __shared__ __align__(16) float Bs[16][68];    // [k][n], stride 272B

    // ---- P0: zero cnt / cursor / C --------------------------------------
    if (idx < N_) { g_cnt[idx] = 0; g_cursor[idx] = 0; }
    for (int i = idx; i < N_ * B_; i += NBLK * NTHR) g_C[i] = 0.0f;

    gbar(gen0, 1);

    // ---- P1: degree histogram -------------------------------------------
    if (idx < E_) atomicAdd(&g_cnt[ei[E_ + idx]], 1);

    gbar(gen0, 2);

    // ---- P2: scan (block 0) + dis (blocks 1..8) -------------------------
    if (bid == 0) {
        int base = tid * 8;
        int vals[8]; int tot = 0;
#pragma unroll
        for (int j = 0; j < 8; j++) { vals[j] = g_cnt[base + j]; tot += vals[j]; }
        s_scan[tid] = tot;
        __syncthreads();
        for (int off = 1; off < NTHR; off <<= 1) {
            int x = (tid >= off) ? s_scan[tid - off] : 0;
            __syncthreads();
            s_scan[tid] += x;
            __syncthreads();
        }
        int excl = s_scan[tid] - tot;
#pragma unroll
        for (int j = 0; j < 8; j++) { g_offs[base + j] = excl; excl += vals[j]; }
        if (tid == NTHR - 1) g_offs[N_] = excl;
    } else if (bid <= 8) {
        int i = (bid - 1) * NTHR + tid;
        float dv = rsqrtf((float)(g_cnt[i] + 1));   // +1 self-loop
        g_dis[i] = dv;
        g_C[i * B_ + (i >> 7)] = dv * dv;           // self-loop seed
    }

    gbar(gen0, 3);

    // ---- P3: scatter edges into CSR + C; node_mean ----------------------
    if (idx < E_) {
        int u = ei[idx];
        int v = ei[E_ + idx];
        float w = g_dis[u] * g_dis[v];
        int pos = g_offs[v] + atomicAdd(&g_cursor[v], 1);
        g_csr_src[pos] = u;
        g_csr_w[pos]   = w;
        atomicAdd(&g_C[u * B_ + (v >> 7)], w);
    }
    {   // node_mean: 32 nodes/block; lane = 16B chunk, sub = node slot
        const int lane = tid & 63, sub = tid >> 6;   // 64 lanes x 8 subs
        const float inv = 1.0f / (float)P_;
#pragma unroll
        for (int r = 0; r < 4; r++) {
            int n = bid * 32 + r * 8 + sub;
            int b = n >> 7;
            int g = gids[n];
            const float4* base = (const float4*)(dge + ((size_t)(b * P_ * S_ + g)) * D_) + lane;
            float4 v[P_];
#pragma unroll
            for (int p = 0; p < P_; p++) v[p] = base[p * (S_ * D_ / 4)];   // 16 in flight
            float sx = 0, sy = 0, sz = 0, sw = 0;
#pragma unroll
            for (int p = 0; p < P_; p++) { sx += v[p].x; sy += v[p].y; sz += v[p].z; sw += v[p].w; }
            float4 o; o.x = sx * inv; o.y = sy * inv; o.z = sz * inv; o.w = sw * inv;
            ((float4*)g_node_x)[n * (D_ / 4) + lane] = o;
        }
    }

    gbar(gen0, 4);

    // ---- P4: aggregate (gather over CSR); 2 nodes concurrently, no smem -
    {
        const int group = tid >> 8;      // 0..1
        const int d = tid & 255;
#pragma unroll 1
        for (int vv = 0; vv < 16; vv++) {
            int v = bid * 32 + group * 16 + vv;
            int beg = g_offs[v], end = g_offs[v + 1];
            float dv = g_dis[v];
            float acc = dv * dv * g_node_x[v * D_ + d];
            float a0 = 0, a1 = 0, a2 = 0, a3 = 0, a4 = 0, a5 = 0, a6 = 0, a7 = 0;
            int i = beg;
            for (; i + 8 <= end; i += 8) {
                int u0 = g_csr_src[i + 0], u1 = g_csr_src[i + 1];
                int u2 = g_csr_src[i + 2], u3 = g_csr_src[i + 3];
                int u4 = g_csr_src[i + 4], u5 = g_csr_src[i + 5];
                int u6 = g_csr_src[i + 6], u7 = g_csr_src[i + 7];
                float w0 = g_csr_w[i + 0], w1 = g_csr_w[i + 1];
                float w2 = g_csr_w[i + 2], w3 = g_csr_w[i + 3];
                float w4 = g_csr_w[i + 4], w5 = g_csr_w[i + 5];
                float w6 = g_csr_w[i + 6], w7 = g_csr_w[i + 7];
                a0 += w0 * g_node_x[u0 * D_ + d];
                a1 += w1 * g_node_x[u1 * D_ + d];
                a2 += w2 * g_node_x[u2 * D_ + d];
                a3 += w3 * g_node_x[u3 * D_ + d];
                a4 += w4 * g_node_x[u4 * D_ + d];
                a5 += w5 * g_node_x[u5 * D_ + d];
                a6 += w6 * g_node_x[u6 * D_ + d];
                a7 += w7 * g_node_x[u7 * D_ + d];
            }
            for (; i < end; i++) a0 += g_csr_w[i] * g_node_x[g_csr_src[i] * D_ + d];
            acc += ((a0 + a1) + (a2 + a3)) + ((a4 + a5) + (a6 + a7));
            g_agg[v * D_ + d] = acc;
        }
    }

    gbar(gen0, 5);

    // ---- P5: x1 = relu(agg @ W1 + b1); 128x64 tile, 512 thr, FFMA2 ------
    {
        int m0 = (bid >> 2) * 128, n0 = (bid & 3) * 64;
        int tx = tid & 15, ty = tid >> 4;             // ty 0..31
        unsigned long long acc[2][4];
#pragma unroll
        for (int p = 0; p < 2; p++)
#pragma unroll
            for (int j = 0; j < 4; j++) acc[p][j] = 0ull;

        for (int k0 = 0; k0 < 256; k0 += 16) {
            {   // A tile 128x16 -> As transposed; 512 threads x 1 float4
                int m = tid >> 2, kq = (tid & 3) << 2;
                float4 a = *(const float4*)&g_agg[(m0 + m) * 256 + k0 + kq];
                As[kq + 0][m] = a.x; As[kq + 1][m] = a.y;
                As[kq + 2][m] = a.z; As[kq + 3][m] = a.w;
            }
            if (tid < 256) {   // B tile 16x64
                int row = tid >> 4, nq = (tid & 15) << 2;
                *(float4*)&Bs[row][nq] = *(const float4*)&W1[(k0 + row) * 256 + n0 + nq];
            }
            __syncthreads();
#pragma unroll
            for (int kk = 0; kk < 16; kk++) {
                ulonglong2 A0 = *(const ulonglong2*)&As[kk][ty * 4];   // 2 m-pairs
                float4 bv = *(const float4*)&Bs[kk][tx * 4];
                unsigned long long p0 = pk2(bv.x), p1 = pk2(bv.y), p2 = pk2(bv.z), p3 = pk2(bv.w);
                acc[0][0] = ffma2(A0.x, p0, acc[0][0]); acc[0][1] = ffma2(A0.x, p1, acc[0][1]);
                acc[0][2] = ffma2(A0.x, p2, acc[0][2]); acc[0][3] = ffma2(A0.x, p3, acc[0][3]);
                acc[1][0] = ffma2(A0.y, p0, acc[1][0]); acc[1][1] = ffma2(A0.y, p1, acc[1][1]);
                acc[1][2] = ffma2(A0.y, p2, acc[1][2]); acc[1][3] = ffma2(A0.y, p3, acc[1][3]);
            }
            __syncthreads();
        }
        float bb[4];
#pragma unroll
        for (int j = 0; j < 4; j++) bb[j] = b1[n0 + tx * 4 + j];
#pragma unroll
        for (int p = 0; p < 2; p++) {
            int m = m0 + ty * 4 + p * 2;
#pragma unroll
            for (int j = 0; j < 4; j++) {
                float lo = __uint_as_float((unsigned)(acc[p][j] & 0xffffffffull));
                float hi = __uint_as_float((unsigned)(acc[p][j] >> 32));
                int nc = n0 + tx * 4 + j;
                g_x1[m * 256 + nc]       = fmaxf(lo + bb[j], 0.0f);
                g_x1[(m + 1) * 256 + nc] = fmaxf(hi + bb[j], 0.0f);
            }
        }
    }

    gbar(gen0, 6);

    // ---- P6: pool partials: 2 halves x 16 u-rows ------------------------
    {
        int u0 = bid * 32;
        for (int i = tid; i < 32 * 32; i += NTHR) sC[i >> 5][i & 31] = g_C[u0 * 32 + i];
        __syncthreads();
        int half = tid >> 8, d = tid & 255;
        float pacc[32];
#pragma unroll
        for (int b = 0; b < 32; b++) pacc[b] = 0.0f;
        for (int uu = 0; uu < 16; uu++) {
            int us = half * 16 + uu;
            float x = g_x1[(u0 + us) * 256 + d];
#pragma unroll
            for (int b = 0; b < 32; b++) pacc[b] += sC[us][b] * x;
        }
        int slot = bid * 2 + half;
#pragma unroll
        for (int b = 0; b < 32; b++) g_part[slot * (B_ * H_) + b * 256 + d] = pacc[b];
    }

    gbar(gen0, 7);

    // ---- P7: reduce 256 partial slots -> tmp (8 threads per output) -----
    {
        int oid = idx >> 3;          // 0..8191
        int part = idx & 7;
        float s = 0.0f;
        int k0 = part * 32;
#pragma unroll 8
        for (int k = 0; k < 32; k++) s += g_part[(k0 + k) * (B_ * H_) + oid];
        s += __shfl_xor_sync(0xffffffffu, s, 1);
        s += __shfl_xor_sync(0xffffffffu, s, 2);
        s += __shfl_xor_sync(0xffffffffu, s, 4);
        if (part == 0) g_tmp[oid] = s;
    }

    gbar(gen0, 8);

    // ---- P8: out = tmp @ W2 / NG + b2 (8 threads per output) ------------
    {
        int oid = idx >> 3;          // 0..8191
        int part = idx & 7;
        int b = oid >> 8, h = oid & 255;
        const float* tr = g_tmp + b * 256 + part * 32;
        const float* w2 = W2 + (part * 32) * 256 + h;
        float acc = 0.0f;
#pragma unroll 8
        for (int d = 0; d < 32; d++) acc += tr[d] * w2[d * 256];
        acc += __shfl_xor_sync(0xffffffffu, acc, 1);
        acc += __shfl_xor_sync(0xffffffffu, acc, 2);
        acc += __shfl_xor_sync(0xffffffffu, acc, 4);
        if (part == 0) out[oid] = acc * (1.0f / NG_) + b2[h];
    }
}

// ---------------- launch -----------------------------------------------------
extern "C" void kernel_launch(void* const* d_in, const int* in_sizes, int n_in,
                              void* d_out, int out_size) {
    const float* dge  = (const float*)d_in[0];
    const int*   gids = (const int*)  d_in[1];
    const int*   ei   = (const int*)  d_in[2];
    const float* W1   = (const float*)d_in[3];
    const float* b1   = (const float*)d_in[4];
    const float* W2   = (const float*)d_in[5];
    const float* b2   = (const float*)d_in[6];
    float* out = (float*)d_out;

    fused_kernel<<<NBLK, NTHR>>>(dge, gids, ei, W1, b1, W2, b2, out);
}